// round 11
// baseline (speedup 1.0000x reference)
#include <cuda_runtime.h>
#include <cuda_bf16.h>

// PositionEmbeddingSine: out[b, slot, d*64 + 2k + {0,1}] = {sin, cos}(v_d * 10000^(-k/32))
// v_d = coord_d * 2*pi / (s_d - 1 + eps).
//
// b = repeat(arange(n_batches), max_len), M = n_batches*max_len, so the
// scatter row == point index p: output is a sequential 252 MB fp32 stream.
// Store-bound; measured ~6.7 TB/s effective write BW.

#define SCALE_2PI 6.283185307179586f
#define EPS_F 1e-6f
#define LOG2_TEMP 13.287712379549449f   // log2(10000)

// 16 lanes per point, 2 points per thread, 32 points per 256-thread block.
// Lane r produces frequency pairs k=2r,2r+1 for all 3 dims
// -> 6 float4 streaming stores per thread.
__global__ __launch_bounds__(256) void pe_sine_kernel(
    const int4* __restrict__ coords4,
    const int* __restrict__ sx_p,
    const int* __restrict__ sy_p,
    const int* __restrict__ sz_p,
    float* __restrict__ out,
    int M)
{
    __shared__ float invt[32];   // 10000^(-k/32)
    __shared__ float sc[3];      // 2*pi / (s_d - 1 + eps)

    int tid = threadIdx.x;
    if (tid < 32) invt[tid] = exp2f(-(float)tid * (LOG2_TEMP / 32.0f));
    if (tid < 3) {
        int s = (tid == 0) ? *sx_p : (tid == 1) ? *sy_p : *sz_p;
        sc[tid] = SCALE_2PI / ((float)(s - 1) + EPS_F);
    }
    __syncthreads();

    int r = tid & 15;
    float t0 = invt[2 * r];
    float t1 = invt[2 * r + 1];
    float s0 = sc[0], s1 = sc[1], s2 = sc[2];

    // 256 threads = 16 lane-groups of 16 points each iteration.
    int p0 = blockIdx.x * 32 + (tid >> 4);   // points p0 and p0+16

#pragma unroll
    for (int j = 0; j < 2; j++) {
        int p = p0 + 16 * j;
        if (p >= M) return;

        int4 c = __ldg(&coords4[p]);
        float* base = out + (long long)p * 192LL + 4 * r;

        float v0 = (float)c.y * s0;
        float v1 = (float)c.z * s1;
        float v2 = (float)c.w * s2;

        float4 o0, o1, o2;
        __sincosf(v0 * t0, &o0.x, &o0.y);
        __sincosf(v0 * t1, &o0.z, &o0.w);
        __stcs((float4*)(base), o0);
        __sincosf(v1 * t0, &o1.x, &o1.y);
        __sincosf(v1 * t1, &o1.z, &o1.w);
        __stcs((float4*)(base + 64), o1);
        __sincosf(v2 * t0, &o2.x, &o2.y);
        __sincosf(v2 * t1, &o2.z, &o2.w);
        __stcs((float4*)(base + 128), o2);
    }
}

extern "C" void kernel_launch(void* const* d_in, const int* in_sizes, int n_in,
                              void* d_out, int out_size) {
    const int* coords = (const int*)d_in[0];
    const int* sx_p   = (const int*)d_in[1];
    const int* sy_p   = (const int*)d_in[2];
    const int* sz_p   = (const int*)d_in[3];
    float* out = (float*)d_out;

    int M = in_sizes[0] / 4;

    int blocks = (M + 31) / 32;   // 32 points per 256-thread block (2/thread)
    pe_sine_kernel<<<blocks, 256>>>((const int4*)coords, sx_p, sy_p, sz_p,
                                    out, M);
}